// round 2
// baseline (speedup 1.0000x reference)
#include <cuda_runtime.h>

// Problem constants
#define Bb 2
#define Ss 4096
#define Dd 512
#define Hh 8
#define HDh 64
#define MR (Bb * Ss)   // 8192 rows

// Scratch (allocation-free rule: __device__ globals)
__device__ float g_q[(size_t)MR * Dd];
__device__ float g_k[(size_t)MR * Dd];
__device__ float g_v[(size_t)MR * Dd];
__device__ float g_o[(size_t)MR * Dd];

// ---------------------------------------------------------------------------
// SGEMM: C[M,512] = A[M,512] @ W[512,512] + bias, fp32, 128x128x8 tiling,
// 8x8 per thread, 256 threads/block.
// ---------------------------------------------------------------------------
__global__ __launch_bounds__(256) void sgemm_bias(const float* __restrict__ A,
                                                  const float* __restrict__ W,
                                                  const float* __restrict__ bias,
                                                  float* __restrict__ C)
{
    const int K = Dd, N = Dd;
    __shared__ float As[8][128];
    __shared__ float Bs[8][128];
    const int tid  = threadIdx.x;
    const int arow = tid >> 1, acol = (tid & 1) << 2;   // A tile: 128 x 8
    const int brow = tid >> 5, bcol = (tid & 31) << 2;  // B tile: 8 x 128
    const int tx = tid & 15, ty = tid >> 4;

    const float* Ab = A + (size_t)blockIdx.y * 128 * K;
    const float* Wb = W + blockIdx.x * 128;

    float acc[8][8] = {};

    for (int k0 = 0; k0 < K; k0 += 8) {
        float4 av = *(const float4*)(Ab + (size_t)arow * K + k0 + acol);
        As[acol + 0][arow] = av.x;
        As[acol + 1][arow] = av.y;
        As[acol + 2][arow] = av.z;
        As[acol + 3][arow] = av.w;
        *(float4*)&Bs[brow][bcol] =
            *(const float4*)(Wb + (size_t)(k0 + brow) * N + bcol);
        __syncthreads();
#pragma unroll
        for (int kk = 0; kk < 8; kk++) {
            float a[8], b[8];
            *(float4*)&a[0] = *(float4*)&As[kk][ty * 8];
            *(float4*)&a[4] = *(float4*)&As[kk][ty * 8 + 4];
            *(float4*)&b[0] = *(float4*)&Bs[kk][tx * 8];
            *(float4*)&b[4] = *(float4*)&Bs[kk][tx * 8 + 4];
#pragma unroll
            for (int i = 0; i < 8; i++)
#pragma unroll
                for (int j = 0; j < 8; j++)
                    acc[i][j] += a[i] * b[j];
        }
        __syncthreads();
    }

    const int crow0 = blockIdx.y * 128 + ty * 8;
    const int ccol0 = blockIdx.x * 128 + tx * 8;
    float bi[8];
#pragma unroll
    for (int j = 0; j < 8; j++) bi[j] = bias[ccol0 + j];
#pragma unroll
    for (int i = 0; i < 8; i++) {
        float* Crow = C + (size_t)(crow0 + i) * N + ccol0;
        float4 o0, o1;
        o0.x = acc[i][0] + bi[0]; o0.y = acc[i][1] + bi[1];
        o0.z = acc[i][2] + bi[2]; o0.w = acc[i][3] + bi[3];
        o1.x = acc[i][4] + bi[4]; o1.y = acc[i][5] + bi[5];
        o1.z = acc[i][6] + bi[6]; o1.w = acc[i][7] + bi[7];
        *(float4*)(Crow + 0) = o0;
        *(float4*)(Crow + 4) = o1;
    }
}

// ---------------------------------------------------------------------------
// Flash attention, fp32. One block = 64 query rows of one (b,h).
// Online softmax over KV tiles of 64 rows. 256 threads, 4x4 per thread.
// q/k/v kept in [B,S,D] layout; head h occupies cols [h*64, h*64+64).
// ---------------------------------------------------------------------------
__global__ __launch_bounds__(256) void flash_attn()
{
    const int q0 = blockIdx.x * 64;
    const int h  = blockIdx.y;
    const int b  = blockIdx.z;
    const size_t base = (size_t)b * Ss * Dd + (size_t)h * HDh;
    const float* qb = g_q + base;
    const float* kb = g_k + base;
    const float* vb = g_v + base;
    float*       ob = g_o + base;

    // +4 pad keeps 16B alignment for float4 while breaking stride-64 conflicts
    __shared__ float Qt[64][68];  // Qt[d][row]   (transposed)
    __shared__ float Kt[64][68];  // Kt[d][kvrow] (transposed)
    __shared__ float Vs[64][68];  // Vs[kvrow][d]
    __shared__ float Pt[64][68];  // Pt[kvrow][row] (transposed probs)

    const int tid = threadIdx.x;
    const int tx = tid & 15, ty = tid >> 4;

    // Load Q tile (transposed into smem), coalesced float4 from GMEM
    for (int e = tid; e < 64 * 16; e += 256) {
        int r = e >> 4, c4 = (e & 15) << 2;
        float4 v = *(const float4*)(qb + (size_t)(q0 + r) * Dd + c4);
        Qt[c4 + 0][r] = v.x; Qt[c4 + 1][r] = v.y;
        Qt[c4 + 2][r] = v.z; Qt[c4 + 3][r] = v.w;
    }

    float m_i[4], l_i[4], o[4][4];
#pragma unroll
    for (int i = 0; i < 4; i++) {
        m_i[i] = -1e30f;
        l_i[i] = 0.0f;
#pragma unroll
        for (int j = 0; j < 4; j++) o[i][j] = 0.0f;
    }

    for (int j0 = 0; j0 < Ss; j0 += 64) {
        __syncthreads();  // prev iter's PV done (also finishes Q load, iter 0)
        for (int e = tid; e < 64 * 16; e += 256) {
            int r = e >> 4, c4 = (e & 15) << 2;
            float4 kv = *(const float4*)(kb + (size_t)(j0 + r) * Dd + c4);
            Kt[c4 + 0][r] = kv.x; Kt[c4 + 1][r] = kv.y;
            Kt[c4 + 2][r] = kv.z; Kt[c4 + 3][r] = kv.w;
            float4 vv = *(const float4*)(vb + (size_t)(j0 + r) * Dd + c4);
            *(float4*)&Vs[r][c4] = vv;
        }
        __syncthreads();

        // S = Q K^T  (4x4 per thread; broadcast-friendly transposed reads)
        float s[4][4] = {};
#pragma unroll 8
        for (int kk = 0; kk < 64; kk++) {
            float4 qv = *(float4*)&Qt[kk][ty << 2];
            float4 kv = *(float4*)&Kt[kk][tx << 2];
            float q[4] = {qv.x, qv.y, qv.z, qv.w};
            float k[4] = {kv.x, kv.y, kv.z, kv.w};
#pragma unroll
            for (int i = 0; i < 4; i++)
#pragma unroll
                for (int j = 0; j < 4; j++)
                    s[i][j] += q[i] * k[j];
        }
#pragma unroll
        for (int i = 0; i < 4; i++)
#pragma unroll
            for (int j = 0; j < 4; j++)
                s[i][j] *= 0.125f;  // 1/sqrt(64)

        // Online softmax: row reduce across the 16 tx lanes
#pragma unroll
        for (int i = 0; i < 4; i++) {
            float rm = fmaxf(fmaxf(s[i][0], s[i][1]), fmaxf(s[i][2], s[i][3]));
#pragma unroll
            for (int off = 1; off < 16; off <<= 1)
                rm = fmaxf(rm, __shfl_xor_sync(0xffffffffu, rm, off));
            float mnew = fmaxf(m_i[i], rm);
            float corr = __expf(m_i[i] - mnew);
            m_i[i] = mnew;
            float p[4];
            float rs = 0.0f;
#pragma unroll
            for (int j = 0; j < 4; j++) {
                p[j] = __expf(s[i][j] - mnew);
                rs += p[j];
            }
#pragma unroll
            for (int off = 1; off < 16; off <<= 1)
                rs += __shfl_xor_sync(0xffffffffu, rs, off);
            l_i[i] = l_i[i] * corr + rs;
#pragma unroll
            for (int j = 0; j < 4; j++) {
                o[i][j] *= corr;
                Pt[(tx << 2) + j][(ty << 2) + i] = p[j];
            }
        }
        __syncthreads();  // Pt complete before PV reads it

        // O += P V
#pragma unroll 8
        for (int kk = 0; kk < 64; kk++) {
            float4 pv = *(float4*)&Pt[kk][ty << 2];
            float4 vv = *(float4*)&Vs[kk][tx << 2];
            float p[4] = {pv.x, pv.y, pv.z, pv.w};
            float v[4] = {vv.x, vv.y, vv.z, vv.w};
#pragma unroll
            for (int i = 0; i < 4; i++)
#pragma unroll
                for (int j = 0; j < 4; j++)
                    o[i][j] += p[i] * v[j];
        }
    }

    // Normalize and write [b, q0+row, h*64 + col]
#pragma unroll
    for (int i = 0; i < 4; i++) {
        float inv = 1.0f / l_i[i];
        float4 r;
        r.x = o[i][0] * inv; r.y = o[i][1] * inv;
        r.z = o[i][2] * inv; r.w = o[i][3] * inv;
        *(float4*)(ob + (size_t)(q0 + (ty << 2) + i) * Dd + (tx << 2)) = r;
    }
}

// ---------------------------------------------------------------------------
extern "C" void kernel_launch(void* const* d_in, const int* in_sizes, int n_in,
                              void* d_out, int out_size)
{
    const float* x  = (const float*)d_in[0];
    const float* y  = (const float*)d_in[1];
    const float* z  = (const float*)d_in[2];
    const float* Wq = (const float*)d_in[3];
    const float* bq = (const float*)d_in[4];
    const float* Wk = (const float*)d_in[5];
    const float* bk = (const float*)d_in[6];
    const float* Wv = (const float*)d_in[7];
    const float* bv = (const float*)d_in[8];
    const float* Wp = (const float*)d_in[9];
    const float* bp = (const float*)d_in[10];
    float* out = (float*)d_out;

    float *qp, *kp, *vp, *op;
    cudaGetSymbolAddress((void**)&qp, g_q);
    cudaGetSymbolAddress((void**)&kp, g_k);
    cudaGetSymbolAddress((void**)&vp, g_v);
    cudaGetSymbolAddress((void**)&op, g_o);

    dim3 gg(Dd / 128, MR / 128);  // (4, 64)
    sgemm_bias<<<gg, 256>>>(x, Wq, bq, qp);
    sgemm_bias<<<gg, 256>>>(y, Wk, bk, kp);
    sgemm_bias<<<gg, 256>>>(z, Wv, bv, vp);
    flash_attn<<<dim3(Ss / 64, Hh, Bb), 256>>>();
    sgemm_bias<<<gg, 256>>>(op, Wp, bp, out);
}

// round 8
// speedup vs baseline: 2.3765x; 2.3765x over previous
#include <cuda_runtime.h>
#include <cuda_bf16.h>
#include <cstdint>

#define Bb 2
#define Ss 4096
#define Dd 512
#define Hh 8
#define HDh 64
#define MR (Bb * Ss)   // 8192

// ---------------- scratch (allocation-free rule) ----------------
__device__ __nv_bfloat16 g_qh[(size_t)MR * Dd];
__device__ __nv_bfloat16 g_ql[(size_t)MR * Dd];
__device__ __nv_bfloat16 g_kh[(size_t)MR * Dd];
__device__ __nv_bfloat16 g_kl[(size_t)MR * Dd];
__device__ __nv_bfloat16 g_vh[(size_t)MR * Dd];
__device__ __nv_bfloat16 g_vl[(size_t)MR * Dd];
__device__ float         g_o [(size_t)MR * Dd];

// ---------------- warp MMA helpers ----------------
__device__ __forceinline__ uint32_t smem_u32(const void* p) {
    uint32_t a;
    asm("{ .reg .u64 t; cvta.to.shared.u64 t, %1; cvt.u32.u64 %0, t; }"
        : "=r"(a) : "l"(p));
    return a;
}
__device__ __forceinline__ void ldsm_x4(uint32_t& r0, uint32_t& r1, uint32_t& r2,
                                        uint32_t& r3, uint32_t a) {
    asm volatile("ldmatrix.sync.aligned.m8n8.x4.shared.b16 {%0,%1,%2,%3}, [%4];"
                 : "=r"(r0), "=r"(r1), "=r"(r2), "=r"(r3) : "r"(a));
}
__device__ __forceinline__ void ldsm_x2(uint32_t& r0, uint32_t& r1, uint32_t a) {
    asm volatile("ldmatrix.sync.aligned.m8n8.x2.shared.b16 {%0,%1}, [%2];"
                 : "=r"(r0), "=r"(r1) : "r"(a));
}
__device__ __forceinline__ void ldsm_x2t(uint32_t& r0, uint32_t& r1, uint32_t a) {
    asm volatile("ldmatrix.sync.aligned.m8n8.x2.trans.shared.b16 {%0,%1}, [%2];"
                 : "=r"(r0), "=r"(r1) : "r"(a));
}
__device__ __forceinline__ void mma16816(float* c, const uint32_t* a, uint32_t b0, uint32_t b1) {
    asm volatile("mma.sync.aligned.m16n8k16.row.col.f32.bf16.bf16.f32 "
                 "{%0,%1,%2,%3}, {%4,%5,%6,%7}, {%8,%9}, {%0,%1,%2,%3};"
                 : "+f"(c[0]), "+f"(c[1]), "+f"(c[2]), "+f"(c[3])
                 : "r"(a[0]), "r"(a[1]), "r"(a[2]), "r"(a[3]), "r"(b0), "r"(b1));
}
__device__ __forceinline__ uint32_t bpack(float lo, float hi) {
    __nv_bfloat162 t = __floats2bfloat162_rn(lo, hi);
    return *(uint32_t*)&t;
}
__device__ __forceinline__ float bres(float x) {  // residual after bf16 rounding
    return x - __bfloat162float(__float2bfloat16(x));
}

// ---------------------------------------------------------------------------
// fp32 SGEMM (validated in R2): C = A@W + bias
// ---------------------------------------------------------------------------
__global__ __launch_bounds__(256) void sgemm_bias(const float* __restrict__ A,
                                                  const float* __restrict__ W,
                                                  const float* __restrict__ bias,
                                                  float* __restrict__ C)
{
    const int K = Dd, N = Dd;
    __shared__ float As[8][128];
    __shared__ float Bs[8][128];
    const int tid  = threadIdx.x;
    const int arow = tid >> 1, acol = (tid & 1) << 2;
    const int brow = tid >> 5, bcol = (tid & 31) << 2;
    const int tx = tid & 15, ty = tid >> 4;

    const float* Ab = A + (size_t)blockIdx.y * 128 * K;
    const float* Wb = W + blockIdx.x * 128;
    float acc[8][8] = {};

    for (int k0 = 0; k0 < K; k0 += 8) {
        float4 av = *(const float4*)(Ab + (size_t)arow * K + k0 + acol);
        As[acol + 0][arow] = av.x; As[acol + 1][arow] = av.y;
        As[acol + 2][arow] = av.z; As[acol + 3][arow] = av.w;
        *(float4*)&Bs[brow][bcol] = *(const float4*)(Wb + (size_t)(k0 + brow) * N + bcol);
        __syncthreads();
#pragma unroll
        for (int kk = 0; kk < 8; kk++) {
            float a[8], b[8];
            *(float4*)&a[0] = *(float4*)&As[kk][ty * 8];
            *(float4*)&a[4] = *(float4*)&As[kk][ty * 8 + 4];
            *(float4*)&b[0] = *(float4*)&Bs[kk][tx * 8];
            *(float4*)&b[4] = *(float4*)&Bs[kk][tx * 8 + 4];
#pragma unroll
            for (int i = 0; i < 8; i++)
#pragma unroll
                for (int j = 0; j < 8; j++)
                    acc[i][j] += a[i] * b[j];
        }
        __syncthreads();
    }
    const int crow0 = blockIdx.y * 128 + ty * 8;
    const int ccol0 = blockIdx.x * 128 + tx * 8;
    float bi[8];
#pragma unroll
    for (int j = 0; j < 8; j++) bi[j] = bias[ccol0 + j];
#pragma unroll
    for (int i = 0; i < 8; i++) {
        float* Crow = C + (size_t)(crow0 + i) * N + ccol0;
        float4 o0, o1;
        o0.x = acc[i][0] + bi[0]; o0.y = acc[i][1] + bi[1];
        o0.z = acc[i][2] + bi[2]; o0.w = acc[i][3] + bi[3];
        o1.x = acc[i][4] + bi[4]; o1.y = acc[i][5] + bi[5];
        o1.z = acc[i][6] + bi[6]; o1.w = acc[i][7] + bi[7];
        *(float4*)(Crow + 0) = o0; *(float4*)(Crow + 4) = o1;
    }
}

// ---------------------------------------------------------------------------
// Same GEMM core, epilogue writes split bf16 hi/lo.
// ---------------------------------------------------------------------------
__global__ __launch_bounds__(256) void sgemm_bias_split(const float* __restrict__ A,
                                                        const float* __restrict__ W,
                                                        const float* __restrict__ bias,
                                                        __nv_bfloat16* __restrict__ Ch,
                                                        __nv_bfloat16* __restrict__ Cl)
{
    const int K = Dd, N = Dd;
    __shared__ float As[8][128];
    __shared__ float Bs[8][128];
    const int tid  = threadIdx.x;
    const int arow = tid >> 1, acol = (tid & 1) << 2;
    const int brow = tid >> 5, bcol = (tid & 31) << 2;
    const int tx = tid & 15, ty = tid >> 4;

    const float* Ab = A + (size_t)blockIdx.y * 128 * K;
    const float* Wb = W + blockIdx.x * 128;
    float acc[8][8] = {};

    for (int k0 = 0; k0 < K; k0 += 8) {
        float4 av = *(const float4*)(Ab + (size_t)arow * K + k0 + acol);
        As[acol + 0][arow] = av.x; As[acol + 1][arow] = av.y;
        As[acol + 2][arow] = av.z; As[acol + 3][arow] = av.w;
        *(float4*)&Bs[brow][bcol] = *(const float4*)(Wb + (size_t)(k0 + brow) * N + bcol);
        __syncthreads();
#pragma unroll
        for (int kk = 0; kk < 8; kk++) {
            float a[8], b[8];
            *(float4*)&a[0] = *(float4*)&As[kk][ty * 8];
            *(float4*)&a[4] = *(float4*)&As[kk][ty * 8 + 4];
            *(float4*)&b[0] = *(float4*)&Bs[kk][tx * 8];
            *(float4*)&b[4] = *(float4*)&Bs[kk][tx * 8 + 4];
#pragma unroll
            for (int i = 0; i < 8; i++)
#pragma unroll
                for (int j = 0; j < 8; j++)
                    acc[i][j] += a[i] * b[j];
        }
        __syncthreads();
    }
    const int crow0 = blockIdx.y * 128 + ty * 8;
    const int ccol0 = blockIdx.x * 128 + tx * 8;
    float bi[8];
#pragma unroll
    for (int j = 0; j < 8; j++) bi[j] = bias[ccol0 + j];
#pragma unroll
    for (int i = 0; i < 8; i++) {
        union { __nv_bfloat162 b2[4]; uint4 u; } hh, ll;
#pragma unroll
        for (int j = 0; j < 4; j++) {
            float v0 = acc[i][2 * j]     + bi[2 * j];
            float v1 = acc[i][2 * j + 1] + bi[2 * j + 1];
            __nv_bfloat16 h0 = __float2bfloat16(v0);
            __nv_bfloat16 h1 = __float2bfloat16(v1);
            __nv_bfloat16 l0 = __float2bfloat16(v0 - __bfloat162float(h0));
            __nv_bfloat16 l1 = __float2bfloat16(v1 - __bfloat162float(h1));
            hh.b2[j] = __halves2bfloat162(h0, h1);
            ll.b2[j] = __halves2bfloat162(l0, l1);
        }
        *(uint4*)(Ch + (size_t)(crow0 + i) * N + ccol0) = hh.u;
        *(uint4*)(Cl + (size_t)(crow0 + i) * N + ccol0) = ll.u;
    }
}

// ---------------------------------------------------------------------------
// Flash attention on tensor cores: mma.sync m16n8k16 bf16, split hi/lo.
// Block = 128 threads (4 warps), Br=64 query rows of one (b,h), Bc=64.
// Warp w owns rows [w*16, w*16+16). S accum fp32 in registers, online softmax.
// ---------------------------------------------------------------------------
#define STR 72          // smem row stride in bf16 elems (144B, conflict-free LDSM)
#define TSZ (64 * STR)  // one 64-row tile region

__global__ __launch_bounds__(128) void flash_mma()
{
    __shared__ alignas(16) __nv_bfloat16 sm[4 * TSZ];  // 36,864 B

    const int tid  = threadIdx.x;
    const int wid  = tid >> 5;
    const int lane = tid & 31;
    const int q0 = blockIdx.x * 64;
    const int h  = blockIdx.y;
    const int b  = blockIdx.z;

    const uint32_t smb = smem_u32(sm);

    // ---- Load Q tile hi/lo into smem (Q region reuses KV space pre-loop) ----
    {
        const __nv_bfloat16* qh = g_qh + ((size_t)(b * Ss + q0)) * Dd + h * HDh;
        const __nv_bfloat16* ql = g_ql + ((size_t)(b * Ss + q0)) * Dd + h * HDh;
#pragma unroll
        for (int i = 0; i < 4; i++) {
            int idx = i * 128 + tid;
            int r = idx >> 3, c8 = (idx & 7) << 3;
            *(uint4*)&sm[r * STR + c8]       = *(const uint4*)(qh + (size_t)r * Dd + c8);
            *(uint4*)&sm[TSZ + r * STR + c8] = *(const uint4*)(ql + (size_t)r * Dd + c8);
        }
    }
    __syncthreads();

    // ---- Extract persistent Q fragments (4 k-steps, hi+lo) ----
    const int m0 = wid * 16;
    uint32_t aQh[4][4], aQl[4][4];
#pragma unroll
    for (int ks = 0; ks < 4; ks++) {
        uint32_t eo = (uint32_t)((m0 + (lane & 15)) * STR + ks * 16 + (lane >> 4) * 8);
        ldsm_x4(aQh[ks][0], aQh[ks][1], aQh[ks][2], aQh[ks][3], smb + eo * 2);
        ldsm_x4(aQl[ks][0], aQl[ks][1], aQl[ks][2], aQl[ks][3], smb + (TSZ + eo) * 2);
    }
    __syncthreads();  // Q frags extracted; smem free for K/V

    float o[8][4];
#pragma unroll
    for (int j = 0; j < 8; j++)
#pragma unroll
        for (int c = 0; c < 4; c++) o[j][c] = 0.0f;
    float m0r = -1e30f, m1r = -1e30f, l0r = 0.0f, l1r = 0.0f;

    // ldmatrix lane-address components (computed once)
    const int kb_row = lane & 7;              // B-frag (non-trans): K row in n-tile
    const int kb_kof = ((lane >> 3) & 1) * 8; // k-half select
    const int vb_row = (lane & 7) + ((lane >> 3) & 1) * 8;  // trans: V k-row

    const size_t bh_base = (size_t)b * Ss * Dd + (size_t)h * HDh;

    for (int t = 0; t < Ss / 64; t++) {
        // ---- load K/V tile (hi/lo) ----
        const size_t rb = bh_base + (size_t)t * 64 * Dd;
#pragma unroll
        for (int i = 0; i < 4; i++) {
            int idx = i * 128 + tid;
            int r = idx >> 3, c8 = (idx & 7) << 3;
            uint32_t so = (uint32_t)(r * STR + c8);
            size_t go = rb + (size_t)r * Dd + c8;
            *(uint4*)&sm[so]           = *(const uint4*)(g_kh + go);
            *(uint4*)&sm[so + TSZ]     = *(const uint4*)(g_kl + go);
            *(uint4*)&sm[so + 2 * TSZ] = *(const uint4*)(g_vh + go);
            *(uint4*)&sm[so + 3 * TSZ] = *(const uint4*)(g_vl + go);
        }
        __syncthreads();

        // ---- S = Q K^T  (3 split terms), fp32 accum ----
        float p[8][4];
#pragma unroll
        for (int j = 0; j < 8; j++)
#pragma unroll
            for (int c = 0; c < 4; c++) p[j][c] = 0.0f;

#pragma unroll
        for (int ks = 0; ks < 4; ks++) {
#pragma unroll
            for (int j = 0; j < 8; j++) {
                uint32_t eo = (uint32_t)((j * 8 + kb_row) * STR + ks * 16 + kb_kof);
                uint32_t bh0, bh1, bl0, bl1;
                ldsm_x2(bh0, bh1, smb + eo * 2);
                ldsm_x2(bl0, bl1, smb + (TSZ + eo) * 2);
                mma16816(p[j], aQh[ks], bh0, bh1);
                mma16816(p[j], aQl[ks], bh0, bh1);
                mma16816(p[j], aQh[ks], bl0, bl1);
            }
        }

        // ---- online softmax (rows g and g+8) ----
        float rm0 = -1e30f, rm1 = -1e30f;
#pragma unroll
        for (int j = 0; j < 8; j++) {
            p[j][0] *= 0.125f; p[j][1] *= 0.125f;
            p[j][2] *= 0.125f; p[j][3] *= 0.125f;
            rm0 = fmaxf(rm0, fmaxf(p[j][0], p[j][1]));
            rm1 = fmaxf(rm1, fmaxf(p[j][2], p[j][3]));
        }
#pragma unroll
        for (int off = 1; off < 4; off <<= 1) {
            rm0 = fmaxf(rm0, __shfl_xor_sync(0xffffffffu, rm0, off));
            rm1 = fmaxf(rm1, __shfl_xor_sync(0xffffffffu, rm1, off));
        }
        float mn0 = fmaxf(m0r, rm0), mn1 = fmaxf(m1r, rm1);
        float cr0 = __expf(m0r - mn0), cr1 = __expf(m1r - mn1);
        m0r = mn0; m1r = mn1;

        float rs0 = 0.0f, rs1 = 0.0f;
#pragma unroll
        for (int j = 0; j < 8; j++) {
            p[j][0] = __expf(p[j][0] - mn0); rs0 += p[j][0];
            p[j][1] = __expf(p[j][1] - mn0); rs0 += p[j][1];
            p[j][2] = __expf(p[j][2] - mn1); rs1 += p[j][2];
            p[j][3] = __expf(p[j][3] - mn1); rs1 += p[j][3];
        }
#pragma unroll
        for (int off = 1; off < 4; off <<= 1) {
            rs0 += __shfl_xor_sync(0xffffffffu, rs0, off);
            rs1 += __shfl_xor_sync(0xffffffffu, rs1, off);
        }
        l0r = l0r * cr0 + rs0;
        l1r = l1r * cr1 + rs1;
#pragma unroll
        for (int j = 0; j < 8; j++) {
            o[j][0] *= cr0; o[j][1] *= cr0;
            o[j][2] *= cr1; o[j][3] *= cr1;
        }

        // ---- O += P V (3 split terms); P frags built from p registers ----
#pragma unroll
        for (int jp = 0; jp < 4; jp++) {
            const float* pa = p[2 * jp];
            const float* pb = p[2 * jp + 1];
            uint32_t ah[4], al[4];
            ah[0] = bpack(pa[0], pa[1]); ah[1] = bpack(pa[2], pa[3]);
            ah[2] = bpack(pb[0], pb[1]); ah[3] = bpack(pb[2], pb[3]);
            al[0] = bpack(bres(pa[0]), bres(pa[1]));
            al[1] = bpack(bres(pa[2]), bres(pa[3]));
            al[2] = bpack(bres(pb[0]), bres(pb[1]));
            al[3] = bpack(bres(pb[2]), bres(pb[3]));
#pragma unroll
            for (int jj = 0; jj < 8; jj++) {
                uint32_t eo = (uint32_t)((jp * 16 + vb_row) * STR + jj * 8);
                uint32_t vh0, vh1, vl0, vl1;
                ldsm_x2t(vh0, vh1, smb + (2 * TSZ + eo) * 2);
                ldsm_x2t(vl0, vl1, smb + (3 * TSZ + eo) * 2);
                mma16816(o[jj], ah, vh0, vh1);
                mma16816(o[jj], al, vh0, vh1);
                mma16816(o[jj], ah, vl0, vl1);
            }
        }
        __syncthreads();  // PV reads done before next tile overwrites smem
    }

    // ---- epilogue: normalize, write fp32 ----
    const float inv0 = 1.0f / l0r, inv1 = 1.0f / l1r;
    const int g = lane >> 2, tg = lane & 3;
    const size_t row0 = (size_t)b * Ss + q0 + m0 + g;
    const size_t row1 = row0 + 8;
#pragma unroll
    for (int jj = 0; jj < 8; jj++) {
        const int col = h * HDh + jj * 8 + tg * 2;
        float2 v0 = make_float2(o[jj][0] * inv0, o[jj][1] * inv0);
        float2 v1 = make_float2(o[jj][2] * inv1, o[jj][3] * inv1);
        *(float2*)(g_o + row0 * Dd + col) = v0;
        *(float2*)(g_o + row1 * Dd + col) = v1;
    }
}

// ---------------------------------------------------------------------------
extern "C" void kernel_launch(void* const* d_in, const int* in_sizes, int n_in,
                              void* d_out, int out_size)
{
    const float* x  = (const float*)d_in[0];
    const float* y  = (const float*)d_in[1];
    const float* z  = (const float*)d_in[2];
    const float* Wq = (const float*)d_in[3];
    const float* bq = (const float*)d_in[4];
    const float* Wk = (const float*)d_in[5];
    const float* bk = (const float*)d_in[6];
    const float* Wv = (const float*)d_in[7];
    const float* bv = (const float*)d_in[8];
    const float* Wp = (const float*)d_in[9];
    const float* bp = (const float*)d_in[10];
    float* out = (float*)d_out;

    __nv_bfloat16 *qh, *ql, *kh, *kl, *vh, *vl;
    float *op;
    cudaGetSymbolAddress((void**)&qh, g_qh);
    cudaGetSymbolAddress((void**)&ql, g_ql);
    cudaGetSymbolAddress((void**)&kh, g_kh);
    cudaGetSymbolAddress((void**)&kl, g_kl);
    cudaGetSymbolAddress((void**)&vh, g_vh);
    cudaGetSymbolAddress((void**)&vl, g_vl);
    cudaGetSymbolAddress((void**)&op, g_o);

    dim3 gg(Dd / 128, MR / 128);  // (4, 64)
    sgemm_bias_split<<<gg, 256>>>(x, Wq, bq, qh, ql);
    sgemm_bias_split<<<gg, 256>>>(y, Wk, bk, kh, kl);
    sgemm_bias_split<<<gg, 256>>>(z, Wv, bv, vh, vl);
    flash_mma<<<dim3(Ss / 64, Hh, Bb), 128>>>();
    sgemm_bias<<<gg, 256>>>(op, Wp, bp, out);
}

// round 9
// speedup vs baseline: 2.8138x; 1.1840x over previous
#include <cuda_runtime.h>
#include <cuda_bf16.h>
#include <cstdint>

#define Bb 2
#define Ss 4096
#define Dd 512
#define Hh 8
#define HDh 64
#define MR (Bb * Ss)   // 8192

// ---------------- scratch (allocation-free rule) ----------------
__device__ __nv_bfloat16 g_qh[(size_t)MR * Dd];
__device__ __nv_bfloat16 g_ql[(size_t)MR * Dd];
__device__ __nv_bfloat16 g_kh[(size_t)MR * Dd];
__device__ __nv_bfloat16 g_kl[(size_t)MR * Dd];
__device__ __nv_bfloat16 g_vh[(size_t)MR * Dd];
__device__ __nv_bfloat16 g_vl[(size_t)MR * Dd];
__device__ float         g_o [(size_t)MR * Dd];

// ---------------- warp MMA helpers ----------------
__device__ __forceinline__ uint32_t smem_u32(const void* p) {
    uint32_t a;
    asm("{ .reg .u64 t; cvta.to.shared.u64 t, %1; cvt.u32.u64 %0, t; }"
        : "=r"(a) : "l"(p));
    return a;
}
__device__ __forceinline__ void ldsm_x4(uint32_t& r0, uint32_t& r1, uint32_t& r2,
                                        uint32_t& r3, uint32_t a) {
    asm volatile("ldmatrix.sync.aligned.m8n8.x4.shared.b16 {%0,%1,%2,%3}, [%4];"
                 : "=r"(r0), "=r"(r1), "=r"(r2), "=r"(r3) : "r"(a));
}
__device__ __forceinline__ void ldsm_x4t(uint32_t& r0, uint32_t& r1, uint32_t& r2,
                                         uint32_t& r3, uint32_t a) {
    asm volatile("ldmatrix.sync.aligned.m8n8.x4.trans.shared.b16 {%0,%1,%2,%3}, [%4];"
                 : "=r"(r0), "=r"(r1), "=r"(r2), "=r"(r3) : "r"(a));
}
__device__ __forceinline__ void mma16816(float* c, const uint32_t* a, uint32_t b0, uint32_t b1) {
    asm volatile("mma.sync.aligned.m16n8k16.row.col.f32.bf16.bf16.f32 "
                 "{%0,%1,%2,%3}, {%4,%5,%6,%7}, {%8,%9}, {%0,%1,%2,%3};"
                 : "+f"(c[0]), "+f"(c[1]), "+f"(c[2]), "+f"(c[3])
                 : "r"(a[0]), "r"(a[1]), "r"(a[2]), "r"(a[3]), "r"(b0), "r"(b1));
}
__device__ __forceinline__ uint32_t bpack(float lo, float hi) {
    __nv_bfloat162 t = __floats2bfloat162_rn(lo, hi);
    return *(uint32_t*)&t;
}
__device__ __forceinline__ float bres(float x) {
    return x - __bfloat162float(__float2bfloat16(x));
}

// ---------------------------------------------------------------------------
// HMMA split-bf16 GEMM: C[M,512] = A[M,512] @ W[512,512] + bias, A/W fp32 in
// gmem, converted to (hi,lo) bf16 pairs in smem. 3 MMA terms: Ah*Wh + Al*Wh +
// Ah*Wl, fp32 accumulate. Block 128x128, 8 warps (4M x 2N), warp tile 32x64.
// SPLIT_OUT: write split bf16 hi/lo (for q/k/v); else fp32. `scale` folds
// 1/sqrt(HD) into q.
// ---------------------------------------------------------------------------
#define ASTR 40    // A smem stride (elems): 80B rows, conflict-free LDSM
#define WSTR 136   // W smem stride (elems): 272B rows, conflict-free LDSM-trans

template <bool SPLIT_OUT>
__global__ __launch_bounds__(256) void hgemm_split(const float* __restrict__ A,
                                                   const float* __restrict__ W,
                                                   const float* __restrict__ bias,
                                                   float scale,
                                                   float* __restrict__ Cf,
                                                   __nv_bfloat16* __restrict__ Ch,
                                                   __nv_bfloat16* __restrict__ Cl)
{
    __shared__ alignas(16) __nv_bfloat16 sAh[128 * ASTR];
    __shared__ alignas(16) __nv_bfloat16 sAl[128 * ASTR];
    __shared__ alignas(16) __nv_bfloat16 sWh[32 * WSTR];
    __shared__ alignas(16) __nv_bfloat16 sWl[32 * WSTR];

    const int tid = threadIdx.x, lane = tid & 31, wid = tid >> 5;
    const int wm = wid >> 1, wn = wid & 1;
    const int bx = blockIdx.x, by = blockIdx.y;

    const uint32_t ahb = smem_u32(sAh), alb = smem_u32(sAl);
    const uint32_t whb = smem_u32(sWh), wlb = smem_u32(sWl);

    float acc[2][8][4] = {};

    // ldmatrix address components
    const int a_row = lane & 15, a_k = (lane >> 4) * 8;                 // A x4
    const int w_row = ((lane >> 3) & 1) * 8 + (lane & 7);               // W x4t k-row
    const int w_cj  = (lane >> 4);                                      // W x4t col-half

    for (int k0 = 0; k0 < 512; k0 += 32) {
        __syncthreads();
        // ---- A tile 128x32 fp32 -> split bf16 ----
#pragma unroll
        for (int i = 0; i < 4; i++) {
            int idx = i * 256 + tid;
            int r = idx >> 3, c = (idx & 7) << 2;
            float4 v = *(const float4*)(A + ((size_t)(by * 128 + r)) * 512 + k0 + c);
            __nv_bfloat16 h0 = __float2bfloat16(v.x), h1 = __float2bfloat16(v.y);
            __nv_bfloat16 h2 = __float2bfloat16(v.z), h3 = __float2bfloat16(v.w);
            __nv_bfloat16 l0 = __float2bfloat16(v.x - __bfloat162float(h0));
            __nv_bfloat16 l1 = __float2bfloat16(v.y - __bfloat162float(h1));
            __nv_bfloat16 l2 = __float2bfloat16(v.z - __bfloat162float(h2));
            __nv_bfloat16 l3 = __float2bfloat16(v.w - __bfloat162float(h3));
            uint2 hu, lu;
            { __nv_bfloat162 t = __halves2bfloat162(h0, h1); hu.x = *(uint32_t*)&t; }
            { __nv_bfloat162 t = __halves2bfloat162(h2, h3); hu.y = *(uint32_t*)&t; }
            { __nv_bfloat162 t = __halves2bfloat162(l0, l1); lu.x = *(uint32_t*)&t; }
            { __nv_bfloat162 t = __halves2bfloat162(l2, l3); lu.y = *(uint32_t*)&t; }
            *(uint2*)&sAh[r * ASTR + c] = hu;
            *(uint2*)&sAl[r * ASTR + c] = lu;
        }
        // ---- W tile 32x128 fp32 -> split bf16 ----
#pragma unroll
        for (int i = 0; i < 4; i++) {
            int idx = i * 256 + tid;
            int r = idx >> 5, c = (idx & 31) << 2;
            float4 v = *(const float4*)(W + ((size_t)(k0 + r)) * 512 + bx * 128 + c);
            __nv_bfloat16 h0 = __float2bfloat16(v.x), h1 = __float2bfloat16(v.y);
            __nv_bfloat16 h2 = __float2bfloat16(v.z), h3 = __float2bfloat16(v.w);
            __nv_bfloat16 l0 = __float2bfloat16(v.x - __bfloat162float(h0));
            __nv_bfloat16 l1 = __float2bfloat16(v.y - __bfloat162float(h1));
            __nv_bfloat16 l2 = __float2bfloat16(v.z - __bfloat162float(h2));
            __nv_bfloat16 l3 = __float2bfloat16(v.w - __bfloat162float(h3));
            uint2 hu, lu;
            { __nv_bfloat162 t = __halves2bfloat162(h0, h1); hu.x = *(uint32_t*)&t; }
            { __nv_bfloat162 t = __halves2bfloat162(h2, h3); hu.y = *(uint32_t*)&t; }
            { __nv_bfloat162 t = __halves2bfloat162(l0, l1); lu.x = *(uint32_t*)&t; }
            { __nv_bfloat162 t = __halves2bfloat162(l2, l3); lu.y = *(uint32_t*)&t; }
            *(uint2*)&sWh[r * WSTR + c] = hu;
            *(uint2*)&sWl[r * WSTR + c] = lu;
        }
        __syncthreads();

#pragma unroll
        for (int ks = 0; ks < 2; ks++) {
            uint32_t ah[2][4], al[2][4];
#pragma unroll
            for (int mt = 0; mt < 2; mt++) {
                uint32_t eo = (uint32_t)((wm * 32 + mt * 16 + a_row) * ASTR + ks * 16 + a_k) * 2;
                ldsm_x4(ah[mt][0], ah[mt][1], ah[mt][2], ah[mt][3], ahb + eo);
                ldsm_x4(al[mt][0], al[mt][1], al[mt][2], al[mt][3], alb + eo);
            }
            uint32_t bh[8][2], bl[8][2];
#pragma unroll
            for (int p = 0; p < 4; p++) {
                uint32_t eo = (uint32_t)((ks * 16 + w_row) * WSTR + wn * 64 + (2 * p + w_cj) * 8) * 2;
                ldsm_x4t(bh[2 * p][0], bh[2 * p][1], bh[2 * p + 1][0], bh[2 * p + 1][1], whb + eo);
                ldsm_x4t(bl[2 * p][0], bl[2 * p][1], bl[2 * p + 1][0], bl[2 * p + 1][1], wlb + eo);
            }
#pragma unroll
            for (int mt = 0; mt < 2; mt++)
#pragma unroll
                for (int nj = 0; nj < 8; nj++) {
                    mma16816(acc[mt][nj], ah[mt], bh[nj][0], bh[nj][1]);
                    mma16816(acc[mt][nj], al[mt], bh[nj][0], bh[nj][1]);
                    mma16816(acc[mt][nj], ah[mt], bl[nj][0], bl[nj][1]);
                }
        }
    }

    // ---- epilogue ----
    const int g = lane >> 2, tg = lane & 3;
#pragma unroll
    for (int mt = 0; mt < 2; mt++) {
#pragma unroll
        for (int nj = 0; nj < 8; nj++) {
            const int m = by * 128 + wm * 32 + mt * 16 + g;
            const int n = bx * 128 + wn * 64 + nj * 8 + tg * 2;
            const float b0 = bias[n], b1 = bias[n + 1];
            float v00 = (acc[mt][nj][0] + b0) * scale;
            float v01 = (acc[mt][nj][1] + b1) * scale;
            float v10 = (acc[mt][nj][2] + b0) * scale;
            float v11 = (acc[mt][nj][3] + b1) * scale;
            if (SPLIT_OUT) {
                *(uint32_t*)(Ch + (size_t)m * 512 + n)       = bpack(v00, v01);
                *(uint32_t*)(Ch + (size_t)(m + 8) * 512 + n) = bpack(v10, v11);
                *(uint32_t*)(Cl + (size_t)m * 512 + n)       = bpack(bres(v00), bres(v01));
                *(uint32_t*)(Cl + (size_t)(m + 8) * 512 + n) = bpack(bres(v10), bres(v11));
            } else {
                *(float2*)(Cf + (size_t)m * 512 + n)       = make_float2(v00, v01);
                *(float2*)(Cf + (size_t)(m + 8) * 512 + n) = make_float2(v10, v11);
            }
        }
    }
}

// ---------------------------------------------------------------------------
// Flash attention, mma.sync split-bf16. 1/sqrt(HD) pre-folded into q.
// Block = 128 threads (4 warps), Br=64, Bc=64; warp owns 16 M-rows.
// x4 ldmatrix: one op feeds two n8 b-pairs.
// ---------------------------------------------------------------------------
#define STR 72
#define TSZ (64 * STR)

__global__ __launch_bounds__(128) void flash_mma()
{
    __shared__ alignas(16) __nv_bfloat16 sm[4 * TSZ];  // 36,864 B

    const int tid  = threadIdx.x;
    const int wid  = tid >> 5;
    const int lane = tid & 31;
    const int q0 = blockIdx.x * 64;
    const int h  = blockIdx.y;
    const int b  = blockIdx.z;

    const uint32_t smb = smem_u32(sm);

    // ---- Q tile hi/lo -> smem ----
    {
        const __nv_bfloat16* qh = g_qh + ((size_t)(b * Ss + q0)) * Dd + h * HDh;
        const __nv_bfloat16* ql = g_ql + ((size_t)(b * Ss + q0)) * Dd + h * HDh;
#pragma unroll
        for (int i = 0; i < 4; i++) {
            int idx = i * 128 + tid;
            int r = idx >> 3, c8 = (idx & 7) << 3;
            *(uint4*)&sm[r * STR + c8]       = *(const uint4*)(qh + (size_t)r * Dd + c8);
            *(uint4*)&sm[TSZ + r * STR + c8] = *(const uint4*)(ql + (size_t)r * Dd + c8);
        }
    }
    __syncthreads();

    // ---- persistent Q fragments ----
    const int m0 = wid * 16;
    uint32_t aQh[4][4], aQl[4][4];
#pragma unroll
    for (int ks = 0; ks < 4; ks++) {
        uint32_t eo = (uint32_t)((m0 + (lane & 15)) * STR + ks * 16 + (lane >> 4) * 8);
        ldsm_x4(aQh[ks][0], aQh[ks][1], aQh[ks][2], aQh[ks][3], smb + eo * 2);
        ldsm_x4(aQl[ks][0], aQl[ks][1], aQl[ks][2], aQl[ks][3], smb + (TSZ + eo) * 2);
    }
    __syncthreads();

    float o[8][4];
#pragma unroll
    for (int j = 0; j < 8; j++)
#pragma unroll
        for (int c = 0; c < 4; c++) o[j][c] = 0.0f;
    float m0r = -1e30f, m1r = -1e30f, l0r = 0.0f, l1r = 0.0f;

    // x4 lane-address components
    const int k_jh  = lane >> 4;               // K: j-half within pair
    const int k_row = lane & 7;                // K: row within 8
    const int k_kof = ((lane >> 3) & 1) * 8;   // K: k-half
    const int v_row = ((lane >> 3) & 1) * 8 + (lane & 7);  // V: k-row
    const int v_cj  = lane >> 4;               // V: col-half

    const size_t bh_base = (size_t)b * Ss * Dd + (size_t)h * HDh;

    for (int t = 0; t < Ss / 64; t++) {
        const size_t rb = bh_base + (size_t)t * 64 * Dd;
#pragma unroll
        for (int i = 0; i < 4; i++) {
            int idx = i * 128 + tid;
            int r = idx >> 3, c8 = (idx & 7) << 3;
            uint32_t so = (uint32_t)(r * STR + c8);
            size_t go = rb + (size_t)r * Dd + c8;
            *(uint4*)&sm[so]           = *(const uint4*)(g_kh + go);
            *(uint4*)&sm[so + TSZ]     = *(const uint4*)(g_kl + go);
            *(uint4*)&sm[so + 2 * TSZ] = *(const uint4*)(g_vh + go);
            *(uint4*)&sm[so + 3 * TSZ] = *(const uint4*)(g_vl + go);
        }
        __syncthreads();

        // ---- S = Q K^T (3 terms) ----
        float p[8][4];
#pragma unroll
        for (int j = 0; j < 8; j++)
#pragma unroll
            for (int c = 0; c < 4; c++) p[j][c] = 0.0f;

#pragma unroll
        for (int ks = 0; ks < 4; ks++) {
#pragma unroll
            for (int jp = 0; jp < 4; jp++) {
                uint32_t eo = (uint32_t)(((2 * jp + k_jh) * 8 + k_row) * STR + ks * 16 + k_kof);
                uint32_t h0, h1, h2, h3, l0, l1, l2, l3;
                ldsm_x4(h0, h1, h2, h3, smb + eo * 2);
                ldsm_x4(l0, l1, l2, l3, smb + (TSZ + eo) * 2);
                mma16816(p[2 * jp],     aQh[ks], h0, h1);
                mma16816(p[2 * jp],     aQl[ks], h0, h1);
                mma16816(p[2 * jp],     aQh[ks], l0, l1);
                mma16816(p[2 * jp + 1], aQh[ks], h2, h3);
                mma16816(p[2 * jp + 1], aQl[ks], h2, h3);
                mma16816(p[2 * jp + 1], aQh[ks], l2, l3);
            }
        }

        // ---- online softmax (scale already folded into q) ----
        float rm0 = -1e30f, rm1 = -1e30f;
#pragma unroll
        for (int j = 0; j < 8; j++) {
            rm0 = fmaxf(rm0, fmaxf(p[j][0], p[j][1]));
            rm1 = fmaxf(rm1, fmaxf(p[j][2], p[j][3]));
        }
#pragma unroll
        for (int off = 1; off < 4; off <<= 1) {
            rm0 = fmaxf(rm0, __shfl_xor_sync(0xffffffffu, rm0, off));
            rm1 = fmaxf(rm1, __shfl_xor_sync(0xffffffffu, rm1, off));
        }
        float mn0 = fmaxf(m0r, rm0), mn1 = fmaxf(m1r, rm1);
        float cr0 = __expf(m0r - mn0), cr1 = __expf(m1r - mn1);
        m0r = mn0; m1r = mn1;

        float rs0 = 0.0f, rs1 = 0.0f;
#pragma unroll
        for (int j = 0; j < 8; j++) {
            p[j][0] = __expf(p[j][0] - mn0); rs0 += p[j][0];
            p[j][1] = __expf(p[j][1] - mn0); rs0 += p[j][1];
            p[j][2] = __expf(p[j][2] - mn1); rs1 += p[j][2];
            p[j][3] = __expf(p[j][3] - mn1); rs1 += p[j][3];
        }
#pragma unroll
        for (int off = 1; off < 4; off <<= 1) {
            rs0 += __shfl_xor_sync(0xffffffffu, rs0, off);
            rs1 += __shfl_xor_sync(0xffffffffu, rs1, off);
        }
        l0r = l0r * cr0 + rs0;
        l1r = l1r * cr1 + rs1;
#pragma unroll
        for (int j = 0; j < 8; j++) {
            o[j][0] *= cr0; o[j][1] *= cr0;
            o[j][2] *= cr1; o[j][3] *= cr1;
        }

        // ---- O += P V (3 terms) ----
#pragma unroll
        for (int jp = 0; jp < 4; jp++) {
            const float* pa = p[2 * jp];
            const float* pb = p[2 * jp + 1];
            uint32_t ah[4], al[4];
            ah[0] = bpack(pa[0], pa[1]); ah[1] = bpack(pa[2], pa[3]);
            ah[2] = bpack(pb[0], pb[1]); ah[3] = bpack(pb[2], pb[3]);
            al[0] = bpack(bres(pa[0]), bres(pa[1]));
            al[1] = bpack(bres(pa[2]), bres(pa[3]));
            al[2] = bpack(bres(pb[0]), bres(pb[1]));
            al[3] = bpack(bres(pb[2]), bres(pb[3]));
#pragma unroll
            for (int jj2 = 0; jj2 < 4; jj2++) {
                uint32_t eo = (uint32_t)((jp * 16 + v_row) * STR + (2 * jj2 + v_cj) * 8);
                uint32_t vh0, vh1, vh2, vh3, vl0, vl1, vl2, vl3;
                ldsm_x4t(vh0, vh1, vh2, vh3, smb + (2 * TSZ + eo) * 2);
                ldsm_x4t(vl0, vl1, vl2, vl3, smb + (3 * TSZ + eo) * 2);
                mma16816(o[2 * jj2],     ah, vh0, vh1);
                mma16816(o[2 * jj2],     al, vh0, vh1);
                mma16816(o[2 * jj2],     ah, vl0, vl1);
                mma16816(o[2 * jj2 + 1], ah, vh2, vh3);
                mma16816(o[2 * jj2 + 1], al, vh2, vh3);
                mma16816(o[2 * jj2 + 1], ah, vl2, vl3);
            }
        }
        __syncthreads();
    }

    // ---- epilogue: normalize, write fp32 ----
    const float inv0 = 1.0f / l0r, inv1 = 1.0f / l1r;
    const int g = lane >> 2, tg = lane & 3;
    const size_t row0 = (size_t)b * Ss + q0 + m0 + g;
    const size_t row1 = row0 + 8;
#pragma unroll
    for (int jj = 0; jj < 8; jj++) {
        const int col = h * HDh + jj * 8 + tg * 2;
        float2 v0 = make_float2(o[jj][0] * inv0, o[jj][1] * inv0);
        float2 v1 = make_float2(o[jj][2] * inv1, o[jj][3] * inv1);
        *(float2*)(g_o + row0 * Dd + col) = v0;
        *(float2*)(g_o + row1 * Dd + col) = v1;
    }
}

// ---------------------------------------------------------------------------
extern "C" void kernel_launch(void* const* d_in, const int* in_sizes, int n_in,
                              void* d_out, int out_size)
{
    const float* x  = (const float*)d_in[0];
    const float* y  = (const float*)d_in[1];
    const float* z  = (const float*)d_in[2];
    const float* Wq = (const float*)d_in[3];
    const float* bq = (const float*)d_in[4];
    const float* Wk = (const float*)d_in[5];
    const float* bk = (const float*)d_in[6];
    const float* Wv = (const float*)d_in[7];
    const float* bv = (const float*)d_in[8];
    const float* Wp = (const float*)d_in[9];
    const float* bp = (const float*)d_in[10];
    float* out = (float*)d_out;

    __nv_bfloat16 *qh, *ql, *kh, *kl, *vh, *vl;
    float *op;
    cudaGetSymbolAddress((void**)&qh, g_qh);
    cudaGetSymbolAddress((void**)&ql, g_ql);
    cudaGetSymbolAddress((void**)&kh, g_kh);
    cudaGetSymbolAddress((void**)&kl, g_kl);
    cudaGetSymbolAddress((void**)&vh, g_vh);
    cudaGetSymbolAddress((void**)&vl, g_vl);
    cudaGetSymbolAddress((void**)&op, g_o);

    dim3 gg(Dd / 128, MR / 128);  // (4, 64)
    hgemm_split<true><<<gg, 256>>>(x, Wq, bq, 0.125f, nullptr, qh, ql);
    hgemm_split<true><<<gg, 256>>>(y, Wk, bk, 1.0f,   nullptr, kh, kl);
    hgemm_split<true><<<gg, 256>>>(z, Wv, bv, 1.0f,   nullptr, vh, vl);
    flash_mma<<<dim3(Ss / 64, Hh, Bb), 128>>>();
    hgemm_split<false><<<gg, 256>>>(op, Wp, bp, 1.0f, out, nullptr, nullptr);
}

// round 11
// speedup vs baseline: 3.2580x; 1.1579x over previous
#include <cuda_runtime.h>
#include <cuda_bf16.h>
#include <cstdint>

#define Bb 2
#define Ss 4096
#define Dd 512
#define Hh 8
#define HDh 64
#define MR (Bb * Ss)   // 8192

// ---------------- scratch (allocation-free rule) ----------------
__device__ __nv_bfloat16 g_qh[(size_t)MR * Dd];
__device__ __nv_bfloat16 g_ql[(size_t)MR * Dd];
__device__ __nv_bfloat16 g_kh[(size_t)MR * Dd];
__device__ __nv_bfloat16 g_kl[(size_t)MR * Dd];
__device__ __nv_bfloat16 g_vh[(size_t)MR * Dd];
__device__ __nv_bfloat16 g_vl[(size_t)MR * Dd];
__device__ float         g_o [(size_t)MR * Dd];

// ---------------- warp MMA helpers ----------------
__device__ __forceinline__ uint32_t smem_u32(const void* p) {
    uint32_t a;
    asm("{ .reg .u64 t; cvta.to.shared.u64 t, %1; cvt.u32.u64 %0, t; }"
        : "=r"(a) : "l"(p));
    return a;
}
__device__ __forceinline__ void ldsm_x4(uint32_t& r0, uint32_t& r1, uint32_t& r2,
                                        uint32_t& r3, uint32_t a) {
    asm volatile("ldmatrix.sync.aligned.m8n8.x4.shared.b16 {%0,%1,%2,%3}, [%4];"
                 : "=r"(r0), "=r"(r1), "=r"(r2), "=r"(r3) : "r"(a));
}
__device__ __forceinline__ void ldsm_x4t(uint32_t& r0, uint32_t& r1, uint32_t& r2,
                                         uint32_t& r3, uint32_t a) {
    asm volatile("ldmatrix.sync.aligned.m8n8.x4.trans.shared.b16 {%0,%1,%2,%3}, [%4];"
                 : "=r"(r0), "=r"(r1), "=r"(r2), "=r"(r3) : "r"(a));
}
__device__ __forceinline__ void ldsm_x2(uint32_t& r0, uint32_t& r1, uint32_t a) {
    asm volatile("ldmatrix.sync.aligned.m8n8.x2.shared.b16 {%0,%1}, [%2];"
                 : "=r"(r0), "=r"(r1) : "r"(a));
}
__device__ __forceinline__ void ldsm_x2t(uint32_t& r0, uint32_t& r1, uint32_t a) {
    asm volatile("ldmatrix.sync.aligned.m8n8.x2.trans.shared.b16 {%0,%1}, [%2];"
                 : "=r"(r0), "=r"(r1) : "r"(a));
}
__device__ __forceinline__ void mma16816(float* c, const uint32_t* a, uint32_t b0, uint32_t b1) {
    asm volatile("mma.sync.aligned.m16n8k16.row.col.f32.bf16.bf16.f32 "
                 "{%0,%1,%2,%3}, {%4,%5,%6,%7}, {%8,%9}, {%0,%1,%2,%3};"
                 : "+f"(c[0]), "+f"(c[1]), "+f"(c[2]), "+f"(c[3])
                 : "r"(a[0]), "r"(a[1]), "r"(a[2]), "r"(a[3]), "r"(b0), "r"(b1));
}
__device__ __forceinline__ uint32_t bpack(float lo, float hi) {
    __nv_bfloat162 t = __floats2bfloat162_rn(lo, hi);
    return *(uint32_t*)&t;
}
__device__ __forceinline__ float bres(float x) {
    return x - __bfloat162float(__float2bfloat16(x));
}

// ---------------------------------------------------------------------------
// HMMA split-bf16 GEMM (validated R9): C[M,512] = A[M,512] @ W[512,512] + bias.
// fp32 inputs converted to (hi,lo) bf16 in smem; 3 MMA terms, fp32 accum.
// Block 128x128, 8 warps (4M x 2N), warp tile 32x64.
// ---------------------------------------------------------------------------
#define ASTR 40    // A smem stride (elems)
#define WSTR 136   // W smem stride (elems)

template <bool SPLIT_OUT>
__global__ __launch_bounds__(256) void hgemm_split(const float* __restrict__ A,
                                                   const float* __restrict__ W,
                                                   const float* __restrict__ bias,
                                                   float scale,
                                                   float* __restrict__ Cf,
                                                   __nv_bfloat16* __restrict__ Ch,
                                                   __nv_bfloat16* __restrict__ Cl)
{
    __shared__ alignas(16) __nv_bfloat16 sAh[128 * ASTR];
    __shared__ alignas(16) __nv_bfloat16 sAl[128 * ASTR];
    __shared__ alignas(16) __nv_bfloat16 sWh[32 * WSTR];
    __shared__ alignas(16) __nv_bfloat16 sWl[32 * WSTR];

    const int tid = threadIdx.x, lane = tid & 31, wid = tid >> 5;
    const int wm = wid >> 1, wn = wid & 1;
    const int bx = blockIdx.x, by = blockIdx.y;

    const uint32_t ahb = smem_u32(sAh), alb = smem_u32(sAl);
    const uint32_t whb = smem_u32(sWh), wlb = smem_u32(sWl);

    float acc[2][8][4] = {};

    const int a_row = lane & 15, a_k = (lane >> 4) * 8;
    const int w_row = ((lane >> 3) & 1) * 8 + (lane & 7);
    const int w_cj  = (lane >> 4);

    for (int k0 = 0; k0 < 512; k0 += 32) {
        __syncthreads();
#pragma unroll
        for (int i = 0; i < 4; i++) {
            int idx = i * 256 + tid;
            int r = idx >> 3, c = (idx & 7) << 2;
            float4 v = *(const float4*)(A + ((size_t)(by * 128 + r)) * 512 + k0 + c);
            __nv_bfloat16 h0 = __float2bfloat16(v.x), h1 = __float2bfloat16(v.y);
            __nv_bfloat16 h2 = __float2bfloat16(v.z), h3 = __float2bfloat16(v.w);
            __nv_bfloat16 l0 = __float2bfloat16(v.x - __bfloat162float(h0));
            __nv_bfloat16 l1 = __float2bfloat16(v.y - __bfloat162float(h1));
            __nv_bfloat16 l2 = __float2bfloat16(v.z - __bfloat162float(h2));
            __nv_bfloat16 l3 = __float2bfloat16(v.w - __bfloat162float(h3));
            uint2 hu, lu;
            { __nv_bfloat162 t = __halves2bfloat162(h0, h1); hu.x = *(uint32_t*)&t; }
            { __nv_bfloat162 t = __halves2bfloat162(h2, h3); hu.y = *(uint32_t*)&t; }
            { __nv_bfloat162 t = __halves2bfloat162(l0, l1); lu.x = *(uint32_t*)&t; }
            { __nv_bfloat162 t = __halves2bfloat162(l2, l3); lu.y = *(uint32_t*)&t; }
            *(uint2*)&sAh[r * ASTR + c] = hu;
            *(uint2*)&sAl[r * ASTR + c] = lu;
        }
#pragma unroll
        for (int i = 0; i < 4; i++) {
            int idx = i * 256 + tid;
            int r = idx >> 5, c = (idx & 31) << 2;
            float4 v = *(const float4*)(W + ((size_t)(k0 + r)) * 512 + bx * 128 + c);
            __nv_bfloat16 h0 = __float2bfloat16(v.x), h1 = __float2bfloat16(v.y);
            __nv_bfloat16 h2 = __float2bfloat16(v.z), h3 = __float2bfloat16(v.w);
            __nv_bfloat16 l0 = __float2bfloat16(v.x - __bfloat162float(h0));
            __nv_bfloat16 l1 = __float2bfloat16(v.y - __bfloat162float(h1));
            __nv_bfloat16 l2 = __float2bfloat16(v.z - __bfloat162float(h2));
            __nv_bfloat16 l3 = __float2bfloat16(v.w - __bfloat162float(h3));
            uint2 hu, lu;
            { __nv_bfloat162 t = __halves2bfloat162(h0, h1); hu.x = *(uint32_t*)&t; }
            { __nv_bfloat162 t = __halves2bfloat162(h2, h3); hu.y = *(uint32_t*)&t; }
            { __nv_bfloat162 t = __halves2bfloat162(l0, l1); lu.x = *(uint32_t*)&t; }
            { __nv_bfloat162 t = __halves2bfloat162(l2, l3); lu.y = *(uint32_t*)&t; }
            *(uint2*)&sWh[r * WSTR + c] = hu;
            *(uint2*)&sWl[r * WSTR + c] = lu;
        }
        __syncthreads();

#pragma unroll
        for (int ks = 0; ks < 2; ks++) {
            uint32_t ah[2][4], al[2][4];
#pragma unroll
            for (int mt = 0; mt < 2; mt++) {
                uint32_t eo = (uint32_t)((wm * 32 + mt * 16 + a_row) * ASTR + ks * 16 + a_k) * 2;
                ldsm_x4(ah[mt][0], ah[mt][1], ah[mt][2], ah[mt][3], ahb + eo);
                ldsm_x4(al[mt][0], al[mt][1], al[mt][2], al[mt][3], alb + eo);
            }
            uint32_t bh[8][2], bl[8][2];
#pragma unroll
            for (int p = 0; p < 4; p++) {
                uint32_t eo = (uint32_t)((ks * 16 + w_row) * WSTR + wn * 64 + (2 * p + w_cj) * 8) * 2;
                ldsm_x4t(bh[2 * p][0], bh[2 * p][1], bh[2 * p + 1][0], bh[2 * p + 1][1], whb + eo);
                ldsm_x4t(bl[2 * p][0], bl[2 * p][1], bl[2 * p + 1][0], bl[2 * p + 1][1], wlb + eo);
            }
#pragma unroll
            for (int mt = 0; mt < 2; mt++)
#pragma unroll
                for (int nj = 0; nj < 8; nj++) {
                    mma16816(acc[mt][nj], ah[mt], bh[nj][0], bh[nj][1]);
                    mma16816(acc[mt][nj], al[mt], bh[nj][0], bh[nj][1]);
                    mma16816(acc[mt][nj], ah[mt], bl[nj][0], bl[nj][1]);
                }
        }
    }

    const int g = lane >> 2, tg = lane & 3;
#pragma unroll
    for (int mt = 0; mt < 2; mt++) {
#pragma unroll
        for (int nj = 0; nj < 8; nj++) {
            const int m = by * 128 + wm * 32 + mt * 16 + g;
            const int n = bx * 128 + wn * 64 + nj * 8 + tg * 2;
            const float b0 = bias[n], b1 = bias[n + 1];
            float v00 = (acc[mt][nj][0] + b0) * scale;
            float v01 = (acc[mt][nj][1] + b1) * scale;
            float v10 = (acc[mt][nj][2] + b0) * scale;
            float v11 = (acc[mt][nj][3] + b1) * scale;
            if (SPLIT_OUT) {
                *(uint32_t*)(Ch + (size_t)m * 512 + n)       = bpack(v00, v01);
                *(uint32_t*)(Ch + (size_t)(m + 8) * 512 + n) = bpack(v10, v11);
                *(uint32_t*)(Cl + (size_t)m * 512 + n)       = bpack(bres(v00), bres(v01));
                *(uint32_t*)(Cl + (size_t)(m + 8) * 512 + n) = bpack(bres(v10), bres(v11));
            } else {
                *(float2*)(Cf + (size_t)m * 512 + n)       = make_float2(v00, v01);
                *(float2*)(Cf + (size_t)(m + 8) * 512 + n) = make_float2(v10, v11);
            }
        }
    }
}

// ---------------------------------------------------------------------------
// Flash attention — exact R8 structure (measured 609us, 168 regs, 3 blk/SM),
// scale removed (folded into q projection), residency pinned at 3 blocks/SM.
// ---------------------------------------------------------------------------
#define STR 72
#define TSZ (64 * STR)

__global__ __launch_bounds__(128, 3) void flash_mma()
{
    __shared__ alignas(16) __nv_bfloat16 sm[4 * TSZ];  // 36,864 B

    const int tid  = threadIdx.x;
    const int wid  = tid >> 5;
    const int lane = tid & 31;
    const int q0 = blockIdx.x * 64;
    const int h  = blockIdx.y;
    const int b  = blockIdx.z;

    const uint32_t smb = smem_u32(sm);

    // ---- Q tile hi/lo -> smem (region reused for K/V after frag extract) ----
    {
        const __nv_bfloat16* qh = g_qh + ((size_t)(b * Ss + q0)) * Dd + h * HDh;
        const __nv_bfloat16* ql = g_ql + ((size_t)(b * Ss + q0)) * Dd + h * HDh;
#pragma unroll
        for (int i = 0; i < 4; i++) {
            int idx = i * 128 + tid;
            int r = idx >> 3, c8 = (idx & 7) << 3;
            *(uint4*)&sm[r * STR + c8]       = *(const uint4*)(qh + (size_t)r * Dd + c8);
            *(uint4*)&sm[TSZ + r * STR + c8] = *(const uint4*)(ql + (size_t)r * Dd + c8);
        }
    }
    __syncthreads();

    // ---- persistent Q fragments (4 k-steps, hi+lo) ----
    const int m0 = wid * 16;
    uint32_t aQh[4][4], aQl[4][4];
#pragma unroll
    for (int ks = 0; ks < 4; ks++) {
        uint32_t eo = (uint32_t)((m0 + (lane & 15)) * STR + ks * 16 + (lane >> 4) * 8);
        ldsm_x4(aQh[ks][0], aQh[ks][1], aQh[ks][2], aQh[ks][3], smb + eo * 2);
        ldsm_x4(aQl[ks][0], aQl[ks][1], aQl[ks][2], aQl[ks][3], smb + (TSZ + eo) * 2);
    }
    __syncthreads();

    float o[8][4];
#pragma unroll
    for (int j = 0; j < 8; j++)
#pragma unroll
        for (int c = 0; c < 4; c++) o[j][c] = 0.0f;
    float m0r = -1e30f, m1r = -1e30f, l0r = 0.0f, l1r = 0.0f;

    const int kb_row = lane & 7;
    const int kb_kof = ((lane >> 3) & 1) * 8;
    const int vb_row = (lane & 7) + ((lane >> 3) & 1) * 8;

    const size_t bh_base = (size_t)b * Ss * Dd + (size_t)h * HDh;

    for (int t = 0; t < Ss / 64; t++) {
        const size_t rb = bh_base + (size_t)t * 64 * Dd;
#pragma unroll
        for (int i = 0; i < 4; i++) {
            int idx = i * 128 + tid;
            int r = idx >> 3, c8 = (idx & 7) << 3;
            uint32_t so = (uint32_t)(r * STR + c8);
            size_t go = rb + (size_t)r * Dd + c8;
            *(uint4*)&sm[so]           = *(const uint4*)(g_kh + go);
            *(uint4*)&sm[so + TSZ]     = *(const uint4*)(g_kl + go);
            *(uint4*)&sm[so + 2 * TSZ] = *(const uint4*)(g_vh + go);
            *(uint4*)&sm[so + 3 * TSZ] = *(const uint4*)(g_vl + go);
        }
        __syncthreads();

        // ---- S = Q K^T (3 split terms), scale pre-folded into q ----
        float p[8][4];
#pragma unroll
        for (int j = 0; j < 8; j++)
#pragma unroll
            for (int c = 0; c < 4; c++) p[j][c] = 0.0f;

#pragma unroll
        for (int ks = 0; ks < 4; ks++) {
#pragma unroll
            for (int j = 0; j < 8; j++) {
                uint32_t eo = (uint32_t)((j * 8 + kb_row) * STR + ks * 16 + kb_kof);
                uint32_t bh0, bh1, bl0, bl1;
                ldsm_x2(bh0, bh1, smb + eo * 2);
                ldsm_x2(bl0, bl1, smb + (TSZ + eo) * 2);
                mma16816(p[j], aQh[ks], bh0, bh1);
                mma16816(p[j], aQl[ks], bh0, bh1);
                mma16816(p[j], aQh[ks], bl0, bl1);
            }
        }

        // ---- online softmax ----
        float rm0 = -1e30f, rm1 = -1e30f;
#pragma unroll
        for (int j = 0; j < 8; j++) {
            rm0 = fmaxf(rm0, fmaxf(p[j][0], p[j][1]));
            rm1 = fmaxf(rm1, fmaxf(p[j][2], p[j][3]));
        }
#pragma unroll
        for (int off = 1; off < 4; off <<= 1) {
            rm0 = fmaxf(rm0, __shfl_xor_sync(0xffffffffu, rm0, off));
            rm1 = fmaxf(rm1, __shfl_xor_sync(0xffffffffu, rm1, off));
        }
        float mn0 = fmaxf(m0r, rm0), mn1 = fmaxf(m1r, rm1);
        float cr0 = __expf(m0r - mn0), cr1 = __expf(m1r - mn1);
        m0r = mn0; m1r = mn1;

        float rs0 = 0.0f, rs1 = 0.0f;
#pragma unroll
        for (int j = 0; j < 8; j++) {
            p[j][0] = __expf(p[j][0] - mn0); rs0 += p[j][0];
            p[j][1] = __expf(p[j][1] - mn0); rs0 += p[j][1];
            p[j][2] = __expf(p[j][2] - mn1); rs1 += p[j][2];
            p[j][3] = __expf(p[j][3] - mn1); rs1 += p[j][3];
        }
#pragma unroll
        for (int off = 1; off < 4; off <<= 1) {
            rs0 += __shfl_xor_sync(0xffffffffu, rs0, off);
            rs1 += __shfl_xor_sync(0xffffffffu, rs1, off);
        }
        l0r = l0r * cr0 + rs0;
        l1r = l1r * cr1 + rs1;
#pragma unroll
        for (int j = 0; j < 8; j++) {
            o[j][0] *= cr0; o[j][1] *= cr0;
            o[j][2] *= cr1; o[j][3] *= cr1;
        }

        // ---- O += P V (3 split terms) ----
#pragma unroll
        for (int jp = 0; jp < 4; jp++) {
            const float* pa = p[2 * jp];
            const float* pb = p[2 * jp + 1];
            uint32_t ah[4], al[4];
            ah[0] = bpack(pa[0], pa[1]); ah[1] = bpack(pa[2], pa[3]);
            ah[2] = bpack(pb[0], pb[1]); ah[3] = bpack(pb[2], pb[3]);
            al[0] = bpack(bres(pa[0]), bres(pa[1]));
            al[1] = bpack(bres(pa[2]), bres(pa[3]));
            al[2] = bpack(bres(pb[0]), bres(pb[1]));
            al[3] = bpack(bres(pb[2]), bres(pb[3]));
#pragma unroll
            for (int jj = 0; jj < 8; jj++) {
                uint32_t eo = (uint32_t)((jp * 16 + vb_row) * STR + jj * 8);
                uint32_t vh0, vh1, vl0, vl1;
                ldsm_x2t(vh0, vh1, smb + (2 * TSZ + eo) * 2);
                ldsm_x2t(vl0, vl1, smb + (3 * TSZ + eo) * 2);
                mma16816(o[jj], ah, vh0, vh1);
                mma16816(o[jj], al, vh0, vh1);
                mma16816(o[jj], ah, vl0, vl1);
            }
        }
        __syncthreads();
    }

    // ---- epilogue: normalize, write fp32 ----
    const float inv0 = 1.0f / l0r, inv1 = 1.0f / l1r;
    const int g = lane >> 2, tg = lane & 3;
    const size_t row0 = (size_t)b * Ss + q0 + m0 + g;
    const size_t row1 = row0 + 8;
#pragma unroll
    for (int jj = 0; jj < 8; jj++) {
        const int col = h * HDh + jj * 8 + tg * 2;
        float2 v0 = make_float2(o[jj][0] * inv0, o[jj][1] * inv0);
        float2 v1 = make_float2(o[jj][2] * inv1, o[jj][3] * inv1);
        *(float2*)(g_o + row0 * Dd + col) = v0;
        *(float2*)(g_o + row1 * Dd + col) = v1;
    }
}

// ---------------------------------------------------------------------------
extern "C" void kernel_launch(void* const* d_in, const int* in_sizes, int n_in,
                              void* d_out, int out_size)
{
    const float* x  = (const float*)d_in[0];
    const float* y  = (const float*)d_in[1];
    const float* z  = (const float*)d_in[2];
    const float* Wq = (const float*)d_in[3];
    const float* bq = (const float*)d_in[4];
    const float* Wk = (const float*)d_in[5];
    const float* bk = (const float*)d_in[6];
    const float* Wv = (const float*)d_in[7];
    const float* bv = (const float*)d_in[8];
    const float* Wp = (const float*)d_in[9];
    const float* bp = (const float*)d_in[10];
    float* out = (float*)d_out;

    __nv_bfloat16 *qh, *ql, *kh, *kl, *vh, *vl;
    float *op;
    cudaGetSymbolAddress((void**)&qh, g_qh);
    cudaGetSymbolAddress((void**)&ql, g_ql);
    cudaGetSymbolAddress((void**)&kh, g_kh);
    cudaGetSymbolAddress((void**)&kl, g_kl);
    cudaGetSymbolAddress((void**)&vh, g_vh);
    cudaGetSymbolAddress((void**)&vl, g_vl);
    cudaGetSymbolAddress((void**)&op, g_o);

    dim3 gg(Dd / 128, MR / 128);  // (4, 64)
    hgemm_split<true><<<gg, 256>>>(x, Wq, bq, 0.125f, nullptr, qh, ql);
    hgemm_split<true><<<gg, 256>>>(y, Wk, bk, 1.0f,   nullptr, kh, kl);
    hgemm_split<true><<<gg, 256>>>(z, Wv, bv, 1.0f,   nullptr, vh, vl);
    flash_mma<<<dim3(Ss / 64, Hh, Bb), 128>>>();
    hgemm_split<false><<<gg, 256>>>(op, Wp, bp, 1.0f, out, nullptr, nullptr);
}

// round 12
// speedup vs baseline: 3.4987x; 1.0739x over previous
#include <cuda_runtime.h>
#include <cuda_bf16.h>
#include <cstdint>

#define Bb 2
#define Ss 4096
#define Dd 512
#define Hh 8
#define HDh 64
#define MR (Bb * Ss)   // 8192

// ---------------- scratch (allocation-free rule) ----------------
__device__ __nv_bfloat16 g_qh[(size_t)MR * Dd];
__device__ __nv_bfloat16 g_ql[(size_t)MR * Dd];
__device__ __nv_bfloat16 g_kh[(size_t)MR * Dd];
__device__ __nv_bfloat16 g_kl[(size_t)MR * Dd];
__device__ __nv_bfloat16 g_vh[(size_t)MR * Dd];
__device__ __nv_bfloat16 g_vl[(size_t)MR * Dd];
__device__ float         g_o [(size_t)MR * Dd];

// ---------------- helpers ----------------
__device__ __forceinline__ uint32_t smem_u32(const void* p) {
    uint32_t a;
    asm("{ .reg .u64 t; cvta.to.shared.u64 t, %1; cvt.u32.u64 %0, t; }"
        : "=r"(a) : "l"(p));
    return a;
}
__device__ __forceinline__ void ldsm_x4(uint32_t& r0, uint32_t& r1, uint32_t& r2,
                                        uint32_t& r3, uint32_t a) {
    asm volatile("ldmatrix.sync.aligned.m8n8.x4.shared.b16 {%0,%1,%2,%3}, [%4];"
                 : "=r"(r0), "=r"(r1), "=r"(r2), "=r"(r3) : "r"(a));
}
__device__ __forceinline__ void ldsm_x4t(uint32_t& r0, uint32_t& r1, uint32_t& r2,
                                         uint32_t& r3, uint32_t a) {
    asm volatile("ldmatrix.sync.aligned.m8n8.x4.trans.shared.b16 {%0,%1,%2,%3}, [%4];"
                 : "=r"(r0), "=r"(r1), "=r"(r2), "=r"(r3) : "r"(a));
}
__device__ __forceinline__ void ldsm_x2(uint32_t& r0, uint32_t& r1, uint32_t a) {
    asm volatile("ldmatrix.sync.aligned.m8n8.x2.shared.b16 {%0,%1}, [%2];"
                 : "=r"(r0), "=r"(r1) : "r"(a));
}
__device__ __forceinline__ void ldsm_x2t(uint32_t& r0, uint32_t& r1, uint32_t a) {
    asm volatile("ldmatrix.sync.aligned.m8n8.x2.trans.shared.b16 {%0,%1}, [%2];"
                 : "=r"(r0), "=r"(r1) : "r"(a));
}
__device__ __forceinline__ void mma16816(float* c, const uint32_t* a, uint32_t b0, uint32_t b1) {
    asm volatile("mma.sync.aligned.m16n8k16.row.col.f32.bf16.bf16.f32 "
                 "{%0,%1,%2,%3}, {%4,%5,%6,%7}, {%8,%9}, {%0,%1,%2,%3};"
                 : "+f"(c[0]), "+f"(c[1]), "+f"(c[2]), "+f"(c[3])
                 : "r"(a[0]), "r"(a[1]), "r"(a[2]), "r"(a[3]), "r"(b0), "r"(b1));
}
__device__ __forceinline__ uint32_t bpack(float lo, float hi) {
    __nv_bfloat162 t = __floats2bfloat162_rn(lo, hi);
    return *(uint32_t*)&t;
}
__device__ __forceinline__ float bres(float x) {
    return x - __bfloat162float(__float2bfloat16(x));
}
__device__ __forceinline__ void cp16(uint32_t s, const void* g) {
    asm volatile("cp.async.cg.shared.global [%0], [%1], 16;" :: "r"(s), "l"(g));
}
#define CP_COMMIT() asm volatile("cp.async.commit_group;" ::: "memory")
#define CP_WAIT1()  asm volatile("cp.async.wait_group 1;" ::: "memory")
#define CP_WAIT0()  asm volatile("cp.async.wait_group 0;" ::: "memory")

// ---------------------------------------------------------------------------
// HMMA split-bf16 GEMM (validated R9): C[M,512] = A[M,512] @ W[512,512] + bias.
// ---------------------------------------------------------------------------
#define ASTR 40
#define WSTR 136

template <bool SPLIT_OUT>
__global__ __launch_bounds__(256) void hgemm_split(const float* __restrict__ A,
                                                   const float* __restrict__ W,
                                                   const float* __restrict__ bias,
                                                   float scale,
                                                   float* __restrict__ Cf,
                                                   __nv_bfloat16* __restrict__ Ch,
                                                   __nv_bfloat16* __restrict__ Cl)
{
    __shared__ alignas(16) __nv_bfloat16 sAh[128 * ASTR];
    __shared__ alignas(16) __nv_bfloat16 sAl[128 * ASTR];
    __shared__ alignas(16) __nv_bfloat16 sWh[32 * WSTR];
    __shared__ alignas(16) __nv_bfloat16 sWl[32 * WSTR];

    const int tid = threadIdx.x, lane = tid & 31, wid = tid >> 5;
    const int wm = wid >> 1, wn = wid & 1;
    const int bx = blockIdx.x, by = blockIdx.y;

    const uint32_t ahb = smem_u32(sAh), alb = smem_u32(sAl);
    const uint32_t whb = smem_u32(sWh), wlb = smem_u32(sWl);

    float acc[2][8][4] = {};

    const int a_row = lane & 15, a_k = (lane >> 4) * 8;
    const int w_row = ((lane >> 3) & 1) * 8 + (lane & 7);
    const int w_cj  = (lane >> 4);

    for (int k0 = 0; k0 < 512; k0 += 32) {
        __syncthreads();
#pragma unroll
        for (int i = 0; i < 4; i++) {
            int idx = i * 256 + tid;
            int r = idx >> 3, c = (idx & 7) << 2;
            float4 v = *(const float4*)(A + ((size_t)(by * 128 + r)) * 512 + k0 + c);
            __nv_bfloat16 h0 = __float2bfloat16(v.x), h1 = __float2bfloat16(v.y);
            __nv_bfloat16 h2 = __float2bfloat16(v.z), h3 = __float2bfloat16(v.w);
            __nv_bfloat16 l0 = __float2bfloat16(v.x - __bfloat162float(h0));
            __nv_bfloat16 l1 = __float2bfloat16(v.y - __bfloat162float(h1));
            __nv_bfloat16 l2 = __float2bfloat16(v.z - __bfloat162float(h2));
            __nv_bfloat16 l3 = __float2bfloat16(v.w - __bfloat162float(h3));
            uint2 hu, lu;
            { __nv_bfloat162 t = __halves2bfloat162(h0, h1); hu.x = *(uint32_t*)&t; }
            { __nv_bfloat162 t = __halves2bfloat162(h2, h3); hu.y = *(uint32_t*)&t; }
            { __nv_bfloat162 t = __halves2bfloat162(l0, l1); lu.x = *(uint32_t*)&t; }
            { __nv_bfloat162 t = __halves2bfloat162(l2, l3); lu.y = *(uint32_t*)&t; }
            *(uint2*)&sAh[r * ASTR + c] = hu;
            *(uint2*)&sAl[r * ASTR + c] = lu;
        }
#pragma unroll
        for (int i = 0; i < 4; i++) {
            int idx = i * 256 + tid;
            int r = idx >> 5, c = (idx & 31) << 2;
            float4 v = *(const float4*)(W + ((size_t)(k0 + r)) * 512 + bx * 128 + c);
            __nv_bfloat16 h0 = __float2bfloat16(v.x), h1 = __float2bfloat16(v.y);
            __nv_bfloat16 h2 = __float2bfloat16(v.z), h3 = __float2bfloat16(v.w);
            __nv_bfloat16 l0 = __float2bfloat16(v.x - __bfloat162float(h0));
            __nv_bfloat16 l1 = __float2bfloat16(v.y - __bfloat162float(h1));
            __nv_bfloat16 l2 = __float2bfloat16(v.z - __bfloat162float(h2));
            __nv_bfloat16 l3 = __float2bfloat16(v.w - __bfloat162float(h3));
            uint2 hu, lu;
            { __nv_bfloat162 t = __halves2bfloat162(h0, h1); hu.x = *(uint32_t*)&t; }
            { __nv_bfloat162 t = __halves2bfloat162(h2, h3); hu.y = *(uint32_t*)&t; }
            { __nv_bfloat162 t = __halves2bfloat162(l0, l1); lu.x = *(uint32_t*)&t; }
            { __nv_bfloat162 t = __halves2bfloat162(l2, l3); lu.y = *(uint32_t*)&t; }
            *(uint2*)&sWh[r * WSTR + c] = hu;
            *(uint2*)&sWl[r * WSTR + c] = lu;
        }
        __syncthreads();

#pragma unroll
        for (int ks = 0; ks < 2; ks++) {
            uint32_t ah[2][4], al[2][4];
#pragma unroll
            for (int mt = 0; mt < 2; mt++) {
                uint32_t eo = (uint32_t)((wm * 32 + mt * 16 + a_row) * ASTR + ks * 16 + a_k) * 2;
                ldsm_x4(ah[mt][0], ah[mt][1], ah[mt][2], ah[mt][3], ahb + eo);
                ldsm_x4(al[mt][0], al[mt][1], al[mt][2], al[mt][3], alb + eo);
            }
            uint32_t bh[8][2], bl[8][2];
#pragma unroll
            for (int p = 0; p < 4; p++) {
                uint32_t eo = (uint32_t)((ks * 16 + w_row) * WSTR + wn * 64 + (2 * p + w_cj) * 8) * 2;
                ldsm_x4t(bh[2 * p][0], bh[2 * p][1], bh[2 * p + 1][0], bh[2 * p + 1][1], whb + eo);
                ldsm_x4t(bl[2 * p][0], bl[2 * p][1], bl[2 * p + 1][0], bl[2 * p + 1][1], wlb + eo);
            }
#pragma unroll
            for (int mt = 0; mt < 2; mt++)
#pragma unroll
                for (int nj = 0; nj < 8; nj++) {
                    mma16816(acc[mt][nj], ah[mt], bh[nj][0], bh[nj][1]);
                    mma16816(acc[mt][nj], al[mt], bh[nj][0], bh[nj][1]);
                    mma16816(acc[mt][nj], ah[mt], bl[nj][0], bl[nj][1]);
                }
        }
    }

    const int g = lane >> 2, tg = lane & 3;
#pragma unroll
    for (int mt = 0; mt < 2; mt++) {
#pragma unroll
        for (int nj = 0; nj < 8; nj++) {
            const int m = by * 128 + wm * 32 + mt * 16 + g;
            const int n = bx * 128 + wn * 64 + nj * 8 + tg * 2;
            const float b0 = bias[n], b1 = bias[n + 1];
            float v00 = (acc[mt][nj][0] + b0) * scale;
            float v01 = (acc[mt][nj][1] + b1) * scale;
            float v10 = (acc[mt][nj][2] + b0) * scale;
            float v11 = (acc[mt][nj][3] + b1) * scale;
            if (SPLIT_OUT) {
                *(uint32_t*)(Ch + (size_t)m * 512 + n)       = bpack(v00, v01);
                *(uint32_t*)(Ch + (size_t)(m + 8) * 512 + n) = bpack(v10, v11);
                *(uint32_t*)(Cl + (size_t)m * 512 + n)       = bpack(bres(v00), bres(v01));
                *(uint32_t*)(Cl + (size_t)(m + 8) * 512 + n) = bpack(bres(v10), bres(v11));
            } else {
                *(float2*)(Cf + (size_t)m * 512 + n)       = make_float2(v00, v01);
                *(float2*)(Cf + (size_t)(m + 8) * 512 + n) = make_float2(v10, v11);
            }
        }
    }
}

// ---------------------------------------------------------------------------
// Flash attention — R11 compute body + cp.async double-buffered K/V and
// register-direct Q fragments. Dynamic smem: 2 buffers x (Kh,Kl,Vh,Vl).
// ---------------------------------------------------------------------------
#define STR 72
#define TSZ (64 * STR)
#define TSZB ((uint32_t)(TSZ * 2))        // 9216 B per part
#define FBUF (4 * TSZB)                   // 36864 B per stage
#define FL_SMEM (2 * FBUF)                // 73728 B total

extern __shared__ __nv_bfloat16 fl_dsm[];

__global__ __launch_bounds__(128, 3) void flash_mma()
{
    const int tid  = threadIdx.x;
    const int wid  = tid >> 5;
    const int lane = tid & 31;
    const int q0 = blockIdx.x * 64;
    const int h  = blockIdx.y;
    const int b  = blockIdx.z;

    const uint32_t smb = smem_u32(fl_dsm);
    const size_t bh_base = (size_t)b * Ss * Dd + (size_t)h * HDh;
    const __nv_bfloat16* gkh = g_kh + bh_base;
    const __nv_bfloat16* gkl = g_kl + bh_base;
    const __nv_bfloat16* gvh = g_vh + bh_base;
    const __nv_bfloat16* gvl = g_vl + bh_base;

    // cp.async issue for one KV tile into stage pb
    const int cr = tid >> 3, cc8 = (tid & 7) << 3;   // per-thread 4 chunks of 16 rows
    auto issue_tile = [&](int t, int pb) {
        const size_t rb = (size_t)t * 64 * Dd;
        const uint32_t sb0 = smb + (uint32_t)pb * FBUF;
#pragma unroll
        for (int i = 0; i < 4; i++) {
            int r = cr + i * 16;
            uint32_t so = sb0 + (uint32_t)(r * STR + cc8) * 2;
            size_t go = rb + (size_t)r * Dd + cc8;
            cp16(so,            gkh + go);
            cp16(so + TSZB,     gkl + go);
            cp16(so + 2 * TSZB, gvh + go);
            cp16(so + 3 * TSZB, gvl + go);
        }
        CP_COMMIT();
    };

    // prologue: prefetch tiles 0 and 1
    issue_tile(0, 0);
    issue_tile(1, 1);

    // ---- Q fragments loaded directly from gmem (A-frag layout) ----
    const int m0 = wid * 16;
    const int fg = lane >> 2, ftg = lane & 3;
    uint32_t aQh[4][4], aQl[4][4];
    {
        const size_t qr0 = ((size_t)(b * Ss + q0 + m0 + fg)) * Dd + h * HDh + ftg * 2;
        const size_t qr1 = qr0 + 8 * Dd;
#pragma unroll
        for (int ks = 0; ks < 4; ks++) {
            aQh[ks][0] = *(const uint32_t*)(g_qh + qr0 + ks * 16);
            aQh[ks][1] = *(const uint32_t*)(g_qh + qr1 + ks * 16);
            aQh[ks][2] = *(const uint32_t*)(g_qh + qr0 + ks * 16 + 8);
            aQh[ks][3] = *(const uint32_t*)(g_qh + qr1 + ks * 16 + 8);
            aQl[ks][0] = *(const uint32_t*)(g_ql + qr0 + ks * 16);
            aQl[ks][1] = *(const uint32_t*)(g_ql + qr1 + ks * 16);
            aQl[ks][2] = *(const uint32_t*)(g_ql + qr0 + ks * 16 + 8);
            aQl[ks][3] = *(const uint32_t*)(g_ql + qr1 + ks * 16 + 8);
        }
    }

    float o[8][4];
#pragma unroll
    for (int j = 0; j < 8; j++)
#pragma unroll
        for (int c = 0; c < 4; c++) o[j][c] = 0.0f;
    float m0r = -1e30f, m1r = -1e30f, l0r = 0.0f, l1r = 0.0f;

    const int kb_row = lane & 7;
    const int kb_kof = ((lane >> 3) & 1) * 8;
    const int vb_row = (lane & 7) + ((lane >> 3) & 1) * 8;

    for (int t = 0; t < Ss / 64; t++) {
        const int pb = t & 1;
        const uint32_t kb = smb + (uint32_t)pb * FBUF;

        if (t < Ss / 64 - 1) { CP_WAIT1(); } else { CP_WAIT0(); }
        __syncthreads();

        // ---- S = Q K^T (3 split terms) ----
        float p[8][4];
#pragma unroll
        for (int j = 0; j < 8; j++)
#pragma unroll
            for (int c = 0; c < 4; c++) p[j][c] = 0.0f;

#pragma unroll
        for (int ks = 0; ks < 4; ks++) {
#pragma unroll
            for (int j = 0; j < 8; j++) {
                uint32_t eo = (uint32_t)((j * 8 + kb_row) * STR + ks * 16 + kb_kof) * 2;
                uint32_t bh0, bh1, bl0, bl1;
                ldsm_x2(bh0, bh1, kb + eo);
                ldsm_x2(bl0, bl1, kb + TSZB + eo);
                mma16816(p[j], aQh[ks], bh0, bh1);
                mma16816(p[j], aQl[ks], bh0, bh1);
                mma16816(p[j], aQh[ks], bl0, bl1);
            }
        }

        // ---- online softmax ----
        float rm0 = -1e30f, rm1 = -1e30f;
#pragma unroll
        for (int j = 0; j < 8; j++) {
            rm0 = fmaxf(rm0, fmaxf(p[j][0], p[j][1]));
            rm1 = fmaxf(rm1, fmaxf(p[j][2], p[j][3]));
        }
#pragma unroll
        for (int off = 1; off < 4; off <<= 1) {
            rm0 = fmaxf(rm0, __shfl_xor_sync(0xffffffffu, rm0, off));
            rm1 = fmaxf(rm1, __shfl_xor_sync(0xffffffffu, rm1, off));
        }
        float mn0 = fmaxf(m0r, rm0), mn1 = fmaxf(m1r, rm1);
        float cr0 = __expf(m0r - mn0), cr1 = __expf(m1r - mn1);
        m0r = mn0; m1r = mn1;

        float rs0 = 0.0f, rs1 = 0.0f;
#pragma unroll
        for (int j = 0; j < 8; j++) {
            p[j][0] = __expf(p[j][0] - mn0); rs0 += p[j][0];
            p[j][1] = __expf(p[j][1] - mn0); rs0 += p[j][1];
            p[j][2] = __expf(p[j][2] - mn1); rs1 += p[j][2];
            p[j][3] = __expf(p[j][3] - mn1); rs1 += p[j][3];
        }
#pragma unroll
        for (int off = 1; off < 4; off <<= 1) {
            rs0 += __shfl_xor_sync(0xffffffffu, rs0, off);
            rs1 += __shfl_xor_sync(0xffffffffu, rs1, off);
        }
        l0r = l0r * cr0 + rs0;
        l1r = l1r * cr1 + rs1;
#pragma unroll
        for (int j = 0; j < 8; j++) {
            o[j][0] *= cr0; o[j][1] *= cr0;
            o[j][2] *= cr1; o[j][3] *= cr1;
        }

        // ---- O += P V (3 split terms) ----
#pragma unroll
        for (int jp = 0; jp < 4; jp++) {
            const float* pa = p[2 * jp];
            const float* pb2 = p[2 * jp + 1];
            uint32_t ah[4], al[4];
            ah[0] = bpack(pa[0], pa[1]);  ah[1] = bpack(pa[2], pa[3]);
            ah[2] = bpack(pb2[0], pb2[1]); ah[3] = bpack(pb2[2], pb2[3]);
            al[0] = bpack(bres(pa[0]), bres(pa[1]));
            al[1] = bpack(bres(pa[2]), bres(pa[3]));
            al[2] = bpack(bres(pb2[0]), bres(pb2[1]));
            al[3] = bpack(bres(pb2[2]), bres(pb2[3]));
#pragma unroll
            for (int jj = 0; jj < 8; jj++) {
                uint32_t eo = (uint32_t)((jp * 16 + vb_row) * STR + jj * 8) * 2;
                uint32_t vh0, vh1, vl0, vl1;
                ldsm_x2t(vh0, vh1, kb + 2 * TSZB + eo);
                ldsm_x2t(vl0, vl1, kb + 3 * TSZB + eo);
                mma16816(o[jj], ah, vh0, vh1);
                mma16816(o[jj], al, vh0, vh1);
                mma16816(o[jj], ah, vl0, vl1);
            }
        }
        __syncthreads();  // all warps done with stage pb
        if (t + 2 < Ss / 64) issue_tile(t + 2, pb);
    }

    // ---- epilogue: normalize, write fp32 ----
    const float inv0 = 1.0f / l0r, inv1 = 1.0f / l1r;
    const size_t row0 = (size_t)b * Ss + q0 + m0 + fg;
    const size_t row1 = row0 + 8;
#pragma unroll
    for (int jj = 0; jj < 8; jj++) {
        const int col = h * HDh + jj * 8 + ftg * 2;
        float2 v0 = make_float2(o[jj][0] * inv0, o[jj][1] * inv0);
        float2 v1 = make_float2(o[jj][2] * inv1, o[jj][3] * inv1);
        *(float2*)(g_o + row0 * Dd + col) = v0;
        *(float2*)(g_o + row1 * Dd + col) = v1;
    }
}

// ---------------------------------------------------------------------------
extern "C" void kernel_launch(void* const* d_in, const int* in_sizes, int n_in,
                              void* d_out, int out_size)
{
    const float* x  = (const float*)d_in[0];
    const float* y  = (const float*)d_in[1];
    const float* z  = (const float*)d_in[2];
    const float* Wq = (const float*)d_in[3];
    const float* bq = (const float*)d_in[4];
    const float* Wk = (const float*)d_in[5];
    const float* bk = (const float*)d_in[6];
    const float* Wv = (const float*)d_in[7];
    const float* bv = (const float*)d_in[8];
    const float* Wp = (const float*)d_in[9];
    const float* bp = (const float*)d_in[10];
    float* out = (float*)d_out;

    __nv_bfloat16 *qh, *ql, *kh, *kl, *vh, *vl;
    float *op;
    cudaGetSymbolAddress((void**)&qh, g_qh);
    cudaGetSymbolAddress((void**)&ql, g_ql);
    cudaGetSymbolAddress((void**)&kh, g_kh);
    cudaGetSymbolAddress((void**)&kl, g_kl);
    cudaGetSymbolAddress((void**)&vh, g_vh);
    cudaGetSymbolAddress((void**)&vl, g_vl);
    cudaGetSymbolAddress((void**)&op, g_o);

    // Sticky attribute; set on the (uncaptured) correctness call, no-op later.
    cudaFuncSetAttribute(flash_mma, cudaFuncAttributeMaxDynamicSharedMemorySize,
                         FL_SMEM);

    dim3 gg(Dd / 128, MR / 128);  // (4, 64)
    hgemm_split<true><<<gg, 256>>>(x, Wq, bq, 0.125f, nullptr, qh, ql);
    hgemm_split<true><<<gg, 256>>>(y, Wk, bk, 1.0f,   nullptr, kh, kl);
    hgemm_split<true><<<gg, 256>>>(z, Wv, bv, 1.0f,   nullptr, vh, vl);
    flash_mma<<<dim3(Ss / 64, Hh, Bb), 128, FL_SMEM>>>();
    hgemm_split<false><<<gg, 256>>>(op, Wp, bp, 1.0f, out, nullptr, nullptr);
}